// round 17
// baseline (speedup 1.0000x reference)
#include <cuda_runtime.h>

#define NODES 100000

__device__ unsigned g_deg [NODES];
__device__ float    g_dinv[NODES];
__device__ float4   g_xs  [NODES];   // dinv-scaled input features (layer-1 messages)
__device__ float4   g_acc1[NODES];   // layer-1 aggregation accumulator
__device__ float4   g_gs  [NODES];   // dinv-scaled layer-2 messages (after fused MLP)
__device__ float4   g_acc2[NODES];   // layer-2 aggregation accumulator

__device__ unsigned g_bar_count = 0;
__device__ unsigned g_bar_gen   = 0;

__device__ __forceinline__ void red_add_v4(float4* addr, float4 v) {
    asm volatile("red.global.add.v4.f32 [%0], {%1,%2,%3,%4};"
                 :: "l"(addr), "f"(v.x), "f"(v.y), "f"(v.z), "f"(v.w)
                 : "memory");
}

__device__ __forceinline__ void red_add_u32(unsigned* addr) {
    asm volatile("red.global.add.u32 [%0], 1;" :: "l"(addr) : "memory");
}

// Sense-reversing grid barrier. Counter wraps to 0 via atomicInc (replay-safe);
// gen grows monotonically and is compared by equality (replay-safe).
__device__ __forceinline__ void grid_barrier(unsigned nb) {
    __syncthreads();
    if (threadIdx.x == 0) {
        __threadfence();                       // order my REDs before arrival
        unsigned gen = *(volatile unsigned*)&g_bar_gen;
        unsigned ticket = atomicInc(&g_bar_count, nb - 1u);   // wraps at nb-1
        if (ticket == nb - 1u) {
            atomicAdd(&g_bar_gen, 1u);         // release all waiters
        } else {
            while (*(volatile unsigned*)&g_bar_gen == gen) __nanosleep(64);
        }
        __threadfence();                       // acquire side
    }
    __syncthreads();
}

__global__ void __launch_bounds__(256, 4) k_gcn(
    const float4* __restrict__ x,
    const int* __restrict__ row, const int* __restrict__ col,
    const float* __restrict__ W1, const float* __restrict__ b1,
    const float* __restrict__ W2, const float* __restrict__ b2,
    float4* __restrict__ out, int n, int e, unsigned nb)
{
    __shared__ float sW1T[256];  // [j][i] : sW1T[j*4+i] = W1[i*64+j]
    __shared__ float sW2 [256];  // [j][c] row-major
    __shared__ float sB1 [64];
    int tid = threadIdx.x;

    // Weight staging overlaps phase 1 (no cross-phase dependency).
    sW1T[(tid & 63) * 4 + (tid >> 6)] = W1[tid];  // transpose on load
    sW2[tid] = W2[tid];
    if (tid < 64) sB1[tid] = b1[tid];

    unsigned t0     = blockIdx.x * blockDim.x + tid;
    unsigned stride = gridDim.x * blockDim.x;
    unsigned ue = (unsigned)e, un = (unsigned)n;

    // ── Phase 1: degree count ──
    for (unsigned i = t0; i < ue; i += stride) red_add_u32(&g_deg[col[i]]);
    grid_barrier(nb);

    // ── Phase 2: node pre (dinv, xs, acc1 self-loop init, deg clear) ──
    for (unsigned i = t0; i < un; i += stride) {
        float d = rsqrtf((float)(g_deg[i] + 1u));
        g_deg[i]  = 0u;
        g_dinv[i] = d;
        float4 v = x[i];
        v.x *= d; v.y *= d; v.z *= d; v.w *= d;
        g_xs[i]   = v;
        g_acc1[i] = v;
    }
    grid_barrier(nb);

    // ── Phase 3: layer-1 edge scatter ──
    for (unsigned i = t0; i < ue; i += stride)
        red_add_v4(&g_acc1[col[i]], g_xs[row[i]]);
    grid_barrier(nb);

    // ── Phase 4: fused per-node MLP ──
    {
        const float4* w1t = (const float4*)sW1T;
        const float4* w2  = (const float4*)sW2;
        for (unsigned i = t0; i < un; i += stride) {
            float d = g_dinv[i];
            float4 a = g_acc1[i];
            a.x *= d; a.y *= d; a.z *= d; a.w *= d;
            float4 g = make_float4(0.f, 0.f, 0.f, 0.f);
            #pragma unroll
            for (int j = 0; j < 64; j++) {
                float4 w = w1t[j];
                float4 u = w2[j];
                float h = fmaf(a.x, w.x, fmaf(a.y, w.y, fmaf(a.z, w.z, fmaf(a.w, w.w, sB1[j]))));
                h = fmaxf(h, 0.0f);
                g.x = fmaf(h, u.x, g.x); g.y = fmaf(h, u.y, g.y);
                g.z = fmaf(h, u.z, g.z); g.w = fmaf(h, u.w, g.w);
            }
            float4 s = make_float4(g.x * d, g.y * d, g.z * d, g.w * d);
            g_gs[i]   = s;
            g_acc2[i] = s;
        }
    }
    grid_barrier(nb);

    // ── Phase 5: layer-2 edge scatter ──
    for (unsigned i = t0; i < ue; i += stride)
        red_add_v4(&g_acc2[col[i]], g_gs[row[i]]);
    grid_barrier(nb);

    // ── Phase 6: output ──
    {
        float bx = b2[0], by = b2[1], bz = b2[2], bw = b2[3];
        for (unsigned i = t0; i < un; i += stride) {
            float d = g_dinv[i];
            float4 a = g_acc2[i];
            float4 o;
            o.x = fmaf(d, a.x, bx);
            o.y = fmaf(d, a.y, by);
            o.z = fmaf(d, a.z, bz);
            o.w = fmaf(d, a.w, bw);
            out[i] = o;
        }
    }
}

extern "C" void kernel_launch(void* const* d_in, const int* in_sizes, int n_in,
                              void* d_out, int out_size) {
    const float* x  = (const float*)d_in[0];
    const int*   ei = (const int*)  d_in[1];
    const float* W1 = (const float*)d_in[2];
    const float* b1 = (const float*)d_in[3];
    const float* W2 = (const float*)d_in[4];
    const float* b2 = (const float*)d_in[5];

    int n = in_sizes[0] / 4;   // N nodes (S=4)
    int e = in_sizes[1] / 2;   // E edges
    const int* row = ei;
    const int* col = ei + e;

    // Grid sized to GUARANTEED full residency (barrier liveness).
    int dev = 0;
    cudaGetDevice(&dev);
    int nsm = 0;
    cudaDeviceGetAttribute(&nsm, cudaDevAttrMultiProcessorCount, dev);
    int bpm = 0;
    cudaOccupancyMaxActiveBlocksPerMultiprocessor(&bpm, k_gcn, 256, 0);
    if (bpm > 4) bpm = 4;
    if (bpm < 1) bpm = 1;
    unsigned nb = (unsigned)(nsm * bpm);

    k_gcn<<<nb, 256>>>((const float4*)x, row, col, W1, b1, W2, b2,
                       (float4*)d_out, n, e, nb);
}